// round 5
// baseline (speedup 1.0000x reference)
#include <cuda_runtime.h>
#include <math.h>
#include <stddef.h>

#define Bb   128
#define Ss   256
#define Hh   384
#define NHh  12
#define DHh  32
#define Ff   1536
#define Ll   6
#define TOK  (Bb*Ss)          // 32768 tokens
#define NOFF 5

// ---------------- scratch (device globals; no allocation allowed) ------------
__device__ float g_h  [TOK*Hh];
__device__ float g_q  [TOK*Hh];
__device__ float g_k  [TOK*Hh];
__device__ float g_v  [TOK*Hh];
__device__ float g_ctx[TOK*Hh];
__device__ float g_tmp[TOK*Hh];
__device__ float g_ffn[TOK*Ff];
__device__ float g_pooled[Bb*Hh];
__device__ float g_scores[Bb];
__device__ int   g_exit[Bb];
__device__ int   g_active[Bb];
__device__ float g_activef[Bb];

// ---------------- block mean/var over H=384 (384 threads, 12 warps) ----------
__device__ __forceinline__ float2 block_meanvar(float x) {
    __shared__ float rs[12], rq[12], mv[2];
    float s = x, q = x * x;
    #pragma unroll
    for (int o = 16; o; o >>= 1) {
        s += __shfl_down_sync(0xffffffffu, s, o);
        q += __shfl_down_sync(0xffffffffu, q, o);
    }
    int w = threadIdx.x >> 5;
    if ((threadIdx.x & 31) == 0) { rs[w] = s; rq[w] = q; }
    __syncthreads();
    if (threadIdx.x == 0) {
        float ts = 0.f, tq = 0.f;
        #pragma unroll
        for (int i = 0; i < 12; i++) { ts += rs[i]; tq += rq[i]; }
        float m = ts * (1.0f / Hh);
        float v = tq * (1.0f / Hh) - m * m;
        mv[0] = m; mv[1] = fmaxf(v, 0.0f);
    }
    __syncthreads();
    return make_float2(mv[0], mv[1]);
}

// ---------------- embeddings + LN -------------------------------------------
__global__ void eecx_embed_ln(const int* __restrict__ ids, const int* __restrict__ tt,
                              const float* __restrict__ we, const float* __restrict__ pe,
                              const float* __restrict__ te, const float* __restrict__ g,
                              const float* __restrict__ b) {
    int tok = blockIdx.x, t = threadIdx.x;
    int id = ids[tok];
    int s  = tok % Ss;
    int ty = tt[tok];
    float x = we[(size_t)id * Hh + t] + pe[(size_t)s * Hh + t] + te[(size_t)ty * Hh + t];
    float2 mv = block_meanvar(x);
    g_h[(size_t)tok * Hh + t] = g[t] * (x - mv.x) * rsqrtf(mv.y + 1e-12f) + b[t];
}

// ---------------- residual + LN ---------------------------------------------
__global__ void eecx_add_ln(const float* __restrict__ res, const float* __restrict__ proj,
                            const float* __restrict__ g, const float* __restrict__ b,
                            float* __restrict__ out) {
    int tok = blockIdx.x, t = threadIdx.x;
    size_t idx = (size_t)tok * Hh + t;
    float x = res[idx] + proj[idx];
    float2 mv = block_meanvar(x);
    out[idx] = g[t] * (x - mv.x) * rsqrtf(mv.y + 1e-12f) + b[t];
}

// ---------------- shared SGEMM core -----------------------------------------
// BM=BN=128, BK=16, 256 threads, 8x8 per thread, double-buffered smem with
// register prefetch. Computes one 128x128 C tile. Requires K % 16 == 0.
template <int EPI>
__device__ __forceinline__ void sgemm_tile(
    const float* __restrict__ A,     // [M,K], rows bm..bm+127 used
    const float* __restrict__ W,     // [K,N]
    const float* __restrict__ bias,  // [N]
    float* __restrict__ C,           // [M,N]
    int bm, int bn, int N, int K) {
    const int BK = 16;
    __shared__ float As[2][BK][128];
    __shared__ float Bs[2][BK][128];
    int tid = threadIdx.x;
    int tx = tid & 15, ty = tid >> 4;             // 16x16 thread grid
    int arow = tid >> 1,  acol = (tid & 1) * 4;   // A: 128 rows, k-cols {acol, acol+8}
    int brow = tid >> 5,  bcol = (tid & 31) * 4;  // B: k-rows {brow, brow+8}, 32 float4/row

    float acc[8][8];
    #pragma unroll
    for (int i = 0; i < 8; i++)
        #pragma unroll
        for (int j = 0; j < 8; j++) acc[i][j] = 0.f;

    const float* Aptr = A + (size_t)(bm + arow) * K + acol;
    const float* Wptr = W + (size_t)brow * N + bn + bcol;
    const int ntiles = K / BK;

    // prologue: tile 0 -> buffer 0
    {
        float4 a0 = *(const float4*)(Aptr);
        float4 a1 = *(const float4*)(Aptr + 8);
        float4 b0 = *(const float4*)(Wptr);
        float4 b1 = *(const float4*)(Wptr + (size_t)8 * N);
        As[0][acol + 0][arow] = a0.x; As[0][acol + 1][arow] = a0.y;
        As[0][acol + 2][arow] = a0.z; As[0][acol + 3][arow] = a0.w;
        As[0][acol + 8][arow] = a1.x; As[0][acol + 9][arow] = a1.y;
        As[0][acol +10][arow] = a1.z; As[0][acol +11][arow] = a1.w;
        *(float4*)&Bs[0][brow][bcol]     = b0;
        *(float4*)&Bs[0][brow + 8][bcol] = b1;
    }
    __syncthreads();

    for (int t = 0; t < ntiles; t++) {
        int cur = t & 1, nxt = cur ^ 1;
        float4 apf0, apf1, bpf0, bpf1;
        bool has_next = (t + 1 < ntiles);
        if (has_next) {
            int k0 = (t + 1) * BK;
            apf0 = *(const float4*)(Aptr + k0);
            apf1 = *(const float4*)(Aptr + k0 + 8);
            bpf0 = *(const float4*)(Wptr + (size_t)k0 * N);
            bpf1 = *(const float4*)(Wptr + (size_t)(k0 + 8) * N);
        }
        #pragma unroll
        for (int k = 0; k < BK; k++) {
            float a8[8], b8[8];
            *(float4*)(a8 + 0) = *(const float4*)&As[cur][k][ty * 8 + 0];
            *(float4*)(a8 + 4) = *(const float4*)&As[cur][k][ty * 8 + 4];
            *(float4*)(b8 + 0) = *(const float4*)&Bs[cur][k][tx * 8 + 0];
            *(float4*)(b8 + 4) = *(const float4*)&Bs[cur][k][tx * 8 + 4];
            #pragma unroll
            for (int i = 0; i < 8; i++)
                #pragma unroll
                for (int j = 0; j < 8; j++) acc[i][j] += a8[i] * b8[j];
        }
        if (has_next) {
            As[nxt][acol + 0][arow] = apf0.x; As[nxt][acol + 1][arow] = apf0.y;
            As[nxt][acol + 2][arow] = apf0.z; As[nxt][acol + 3][arow] = apf0.w;
            As[nxt][acol + 8][arow] = apf1.x; As[nxt][acol + 9][arow] = apf1.y;
            As[nxt][acol +10][arow] = apf1.z; As[nxt][acol +11][arow] = apf1.w;
            *(float4*)&Bs[nxt][brow][bcol]     = bpf0;
            *(float4*)&Bs[nxt][brow + 8][bcol] = bpf1;
            __syncthreads();
        }
    }

    #pragma unroll
    for (int i = 0; i < 8; i++) {
        size_t row = bm + ty * 8 + i;
        #pragma unroll
        for (int j = 0; j < 8; j++) {
            int col = bn + tx * 8 + j;
            float val = acc[i][j] + bias[col];
            if (EPI == 1) {  // exact gelu
                val = 0.5f * val * (1.0f + erff(val * 0.70710678118654752440f));
            }
            C[row * N + col] = val;
        }
    }
}

template <int EPI>
__global__ __launch_bounds__(256, 2) void eecx_sgemm(
    const float* __restrict__ A, const float* __restrict__ W,
    const float* __restrict__ bias, float* __restrict__ C,
    int M, int N, int K) {
    sgemm_tile<EPI>(A, W, bias, C, blockIdx.y * 128, blockIdx.x * 128, N, K);
}

// fused QKV: blockIdx.x in [0, 9): mat = x/3 (0=Q,1=K,2=V), tile = x%3
__global__ __launch_bounds__(256, 2) void eecx_sgemm_qkv(
    const float* __restrict__ A,
    const float* __restrict__ wq, const float* __restrict__ wk, const float* __restrict__ wv,
    const float* __restrict__ bq, const float* __restrict__ bk, const float* __restrict__ bv,
    float* __restrict__ q, float* __restrict__ k, float* __restrict__ v) {
    int mat = blockIdx.x / 3, tile = blockIdx.x % 3;
    const float* W; const float* bias; float* C;
    if (mat == 0)      { W = wq; bias = bq; C = q; }
    else if (mat == 1) { W = wk; bias = bk; C = k; }
    else               { W = wv; bias = bv; C = v; }
    sgemm_tile<0>(A, W, bias, C, blockIdx.y * 128, tile * 128, Hh, Hh);
}

// ---------------- attention: one block per (batch, head) --------------------
// dyn smem: ks[256*32], vs[256*32], bias[256]  = 66560 bytes
__global__ __launch_bounds__(256) void eecx_attn(const int* __restrict__ amask) {
    extern __shared__ float sm[];
    float* ks = sm;
    float* vs = sm + Ss * DHh;
    float* bs = vs + Ss * DHh;

    int b = blockIdx.x / NHh, hh = blockIdx.x % NHh;
    int t = threadIdx.x;
    size_t base = ((size_t)b * Ss) * Hh + hh * DHh;

    for (int e = t; e < Ss * (DHh / 4); e += 256) {
        int r = e >> 3, c = (e & 7) * 4;
        *(float4*)&ks[r * DHh + c] = *(const float4*)&g_k[base + (size_t)r * Hh + c];
        *(float4*)&vs[r * DHh + c] = *(const float4*)&g_v[base + (size_t)r * Hh + c];
    }
    bs[t] = (1.0f - (float)amask[b * Ss + t]) * -1e9f;
    __syncthreads();

    // this thread owns query row t
    float q[DHh], o[DHh];
    #pragma unroll
    for (int d = 0; d < DHh; d++) {
        q[d] = g_q[base + (size_t)t * Hh + d];
        o[d] = 0.f;
    }
    float m = -1e30f, l = 0.f;
    const float scale = 0.17677669529663688f;  // 1/sqrt(32)
    for (int j = 0; j < Ss; j++) {
        float s = 0.f;
        #pragma unroll
        for (int d = 0; d < DHh; d++) s += q[d] * ks[j * DHh + d];
        s = s * scale + bs[j];
        float nm = fmaxf(m, s);
        float c = __expf(m - nm);
        float p = __expf(s - nm);
        l = l * c + p;
        #pragma unroll
        for (int d = 0; d < DHh; d++) o[d] = o[d] * c + p * vs[j * DHh + d];
        m = nm;
    }
    float inv = 1.0f / l;
    #pragma unroll
    for (int d = 0; d < DHh; d++)
        g_ctx[base + (size_t)t * Hh + d] = o[d] * inv;
}

// ---------------- early-exit state ------------------------------------------
__global__ void eecx_init_state() {
    int b = threadIdx.x;
    if (b < Bb) { g_active[b] = 1; g_activef[b] = 1.f; g_scores[b] = 0.f; g_exit[b] = 0; }
}

__global__ void eecx_offramp(const float* __restrict__ Wr, const float* __restrict__ br, int layer) {
    int b = blockIdx.x, t = threadIdx.x;  // 128 threads
    __shared__ float sb[4];
    float s = 0.f;
    for (int k = t; k < Hh; k += 128)
        s += g_h[((size_t)b * Ss) * Hh + k] * Wr[layer * Hh + k];
    #pragma unroll
    for (int o = 16; o; o >>= 1) s += __shfl_down_sync(0xffffffffu, s, o);
    if ((t & 31) == 0) sb[t >> 5] = s;
    __syncthreads();
    if (t == 0) {
        float logit = sb[0] + sb[1] + sb[2] + sb[3] + br[layer];
        float a   = fabsf(logit);
        float lp  = fminf(logit, 0.f)  - log1pf(expf(-a));  // log_sigmoid(logit)
        float ln_ = fminf(-logit, 0.f) - log1pf(expf(-a));  // log_sigmoid(-logit)
        float p   = 1.0f / (1.0f + expf(-logit));
        float ent = -(p * lp + (1.0f - p) * ln_);
        if (g_active[b] && ent < 0.1f) {
            g_scores[b] = logit; g_exit[b] = layer;
            g_active[b] = 0;     g_activef[b] = 0.f;
        }
    }
}

__global__ void eecx_mask_h() {  // h *= active (float4 granularity)
    size_t i = (size_t)blockIdx.x * blockDim.x + threadIdx.x;  // TOK*Hh/4 elems
    int b = (int)(i / (Ss * Hh / 4));
    float a = g_activef[b];
    float4* p = (float4*)g_h;
    float4 v = p[i];
    v.x *= a; v.y *= a; v.z *= a; v.w *= a;
    p[i] = v;
}

// ---------------- pooler / classifier / output ------------------------------
__global__ void eecx_pooler(const float* __restrict__ Wp, const float* __restrict__ bp) {
    __shared__ float hs[Hh];
    int b = blockIdx.x, t = threadIdx.x;  // 384 threads
    hs[t] = g_h[((size_t)b * Ss) * Hh + t];
    __syncthreads();
    float s = bp[t];
    for (int k = 0; k < Hh; k++) s += hs[k] * Wp[(size_t)k * Hh + t];
    g_pooled[b * Hh + t] = tanhf(s);
}

__global__ void eecx_classifier(const float* __restrict__ Wc, const float* __restrict__ bc) {
    int b = blockIdx.x, t = threadIdx.x;  // 128 threads
    __shared__ float sb[4];
    float s = 0.f;
    for (int k = t; k < Hh; k += 128) s += g_pooled[b * Hh + k] * Wc[k];
    #pragma unroll
    for (int o = 16; o; o >>= 1) s += __shfl_down_sync(0xffffffffu, s, o);
    if ((t & 31) == 0) sb[t >> 5] = s;
    __syncthreads();
    if (t == 0) {
        float fl = sb[0] + sb[1] + sb[2] + sb[3] + bc[0];
        if (g_active[b]) { g_scores[b] = fl; g_exit[b] = NOFF; }
    }
}

__global__ void eecx_write_out(float* __restrict__ out, int out_size) {
    __shared__ int cnt[NOFF + 1];
    int t = threadIdx.x;  // 256 threads
    if (t <= NOFF) cnt[t] = 0;
    __syncthreads();
    if (t < Bb) atomicAdd(&cnt[g_exit[t]], 1);
    __syncthreads();
    if (t < Bb) {
        if (t < out_size)       out[t]       = g_scores[t];
        if (Bb + t < out_size)  out[Bb + t]  = (float)g_exit[t];
    }
    if (t <= NOFF && 2 * Bb + t < out_size) out[2 * Bb + t] = (float)cnt[t];
}

// ---------------- host ------------------------------------------------------
extern "C" void kernel_launch(void* const* d_in, const int* in_sizes, int n_in,
                              void* d_out, int out_size) {
    const int*   ids   = (const int*)d_in[0];
    const int*   amask = (const int*)d_in[1];
    const int*   tt    = (const int*)d_in[2];
    const float* we    = (const float*)d_in[3];
    const float* pe    = (const float*)d_in[4];
    const float* te    = (const float*)d_in[5];
    const float* eg    = (const float*)d_in[6];
    const float* eb    = (const float*)d_in[7];
    const float* Wq    = (const float*)d_in[8];
    const float* bq    = (const float*)d_in[9];
    const float* Wk    = (const float*)d_in[10];
    const float* bk    = (const float*)d_in[11];
    const float* Wv    = (const float*)d_in[12];
    const float* bv    = (const float*)d_in[13];
    const float* Wo    = (const float*)d_in[14];
    const float* bo    = (const float*)d_in[15];
    const float* g1    = (const float*)d_in[16];
    const float* b1    = (const float*)d_in[17];
    const float* Wi    = (const float*)d_in[18];
    const float* bi    = (const float*)d_in[19];
    const float* Wf    = (const float*)d_in[20];
    const float* bf    = (const float*)d_in[21];
    const float* g2    = (const float*)d_in[22];
    const float* b2    = (const float*)d_in[23];
    const float* Wp    = (const float*)d_in[24];
    const float* bp    = (const float*)d_in[25];
    const float* Wc    = (const float*)d_in[26];
    const float* bc    = (const float*)d_in[27];
    const float* Wr    = (const float*)d_in[28];
    const float* br    = (const float*)d_in[29];
    float* out = (float*)d_out;

    float *ph, *pq, *pk, *pv, *pctx, *ptmp, *pffn;
    cudaGetSymbolAddress((void**)&ph,   g_h);
    cudaGetSymbolAddress((void**)&pq,   g_q);
    cudaGetSymbolAddress((void**)&pk,   g_k);
    cudaGetSymbolAddress((void**)&pv,   g_v);
    cudaGetSymbolAddress((void**)&pctx, g_ctx);
    cudaGetSymbolAddress((void**)&ptmp, g_tmp);
    cudaGetSymbolAddress((void**)&pffn, g_ffn);

    const int ATTN_SMEM = (Ss * DHh * 2 + Ss) * 4;  // 66560 B
    cudaFuncSetAttribute(eecx_attn, cudaFuncAttributeMaxDynamicSharedMemorySize, ATTN_SMEM);

    eecx_init_state<<<1, 128>>>();
    eecx_embed_ln<<<TOK, Hh>>>(ids, tt, we, pe, te, eg, eb);

    dim3 gQKV(9, TOK / 128);        // fused Q,K,V: 3 mats x 3 N-tiles
    dim3 gP(Hh / 128, TOK / 128);   // N=384 single GEMM: 3 x 256
    dim3 gF(Ff / 128, TOK / 128);   // N=1536 FFN up:     12 x 256

    for (int i = 0; i < Ll; i++) {
        const float* wq = Wq + (size_t)i * Hh * Hh;
        const float* wk = Wk + (size_t)i * Hh * Hh;
        const float* wv = Wv + (size_t)i * Hh * Hh;
        const float* wo = Wo + (size_t)i * Hh * Hh;
        const float* wi = Wi + (size_t)i * Hh * Ff;
        const float* wf = Wf + (size_t)i * Ff * Hh;

        eecx_sgemm_qkv<<<gQKV, 256>>>(ph, wq, wk, wv,
                                      bq + i * Hh, bk + i * Hh, bv + i * Hh,
                                      pq, pk, pv);
        eecx_attn<<<Bb * NHh, 256, ATTN_SMEM>>>(amask);
        eecx_sgemm<0><<<gP, 256>>>(pctx, wo, bo + i * Hh, ptmp, TOK, Hh, Hh);
        eecx_add_ln<<<TOK, Hh>>>(ph, ptmp, g1 + i * Hh, b1 + i * Hh, ph);
        eecx_sgemm<1><<<gF, 256>>>(ph, wi, bi + (size_t)i * Ff, pffn, TOK, Ff, Hh);
        eecx_sgemm<0><<<gP, 256>>>(pffn, wf, bf + i * Hh, ptmp, TOK, Hh, Ff);
        eecx_add_ln<<<TOK, Hh>>>(ph, ptmp, g2 + i * Hh, b2 + i * Hh, ph);

        if (i < NOFF) {
            eecx_offramp<<<Bb, 128>>>(Wr, br, i);
            eecx_mask_h<<<(TOK * Hh / 4) / 256, 256>>>();
        }
    }

    eecx_pooler<<<Bb, Hh>>>(Wp, bp);
    eecx_classifier<<<Bb, 128>>>(Wc, bc);
    eecx_write_out<<<1, 256>>>(out, out_size);
}

// round 12
// speedup vs baseline: 1.4370x; 1.4370x over previous
#include <cuda_runtime.h>
#include <cuda_bf16.h>
#include <mma.h>
#include <math.h>
#include <stddef.h>
#include <stdint.h>

using namespace nvcuda;

#define Bb   128
#define Ss   256
#define Hh   384
#define NHh  12
#define DHh  32
#define Ff   1536
#define Ll   6
#define TOK  (Bb*Ss)          // 32768 tokens
#define NOFF 5

// ---------------- scratch (device globals; no allocation allowed) ------------
__device__ float g_h  [TOK*Hh];
__device__ float g_q  [TOK*Hh];
__device__ float g_k  [TOK*Hh];
__device__ float g_v  [TOK*Hh];
__device__ float g_ctx[TOK*Hh];
__device__ float g_tmp[TOK*Hh];
__device__ float g_ffn[TOK*Ff];
__device__ float g_pooled[Bb*Hh];
__device__ float g_scores[Bb];
__device__ int   g_exit[Bb];
__device__ int   g_active[Bb];
__device__ float g_activef[Bb];
// bf16 split buffers (16B-aligned for uint4 access)
__device__ __align__(16) __nv_bfloat16 g_xhi[TOK*Ff];
__device__ __align__(16) __nv_bfloat16 g_xlo[TOK*Ff];
__device__ __align__(16) __nv_bfloat16 g_whiT[Ff*Hh];
__device__ __align__(16) __nv_bfloat16 g_wloT[Ff*Hh];

// ---------------- block mean/var over H=384 (384 threads, 12 warps) ----------
__device__ __forceinline__ float2 block_meanvar(float x) {
    __shared__ float rs[12], rq[12], mv[2];
    float s = x, q = x * x;
    #pragma unroll
    for (int o = 16; o; o >>= 1) {
        s += __shfl_down_sync(0xffffffffu, s, o);
        q += __shfl_down_sync(0xffffffffu, q, o);
    }
    int w = threadIdx.x >> 5;
    if ((threadIdx.x & 31) == 0) { rs[w] = s; rq[w] = q; }
    __syncthreads();
    if (threadIdx.x == 0) {
        float ts = 0.f, tq = 0.f;
        #pragma unroll
        for (int i = 0; i < 12; i++) { ts += rs[i]; tq += rq[i]; }
        float m = ts * (1.0f / Hh);
        float v = tq * (1.0f / Hh) - m * m;
        mv[0] = m; mv[1] = fmaxf(v, 0.0f);
    }
    __syncthreads();
    return make_float2(mv[0], mv[1]);
}

// ---------------- embeddings + LN -------------------------------------------
__global__ void eecx_embed_ln(const int* __restrict__ ids, const int* __restrict__ tt,
                              const float* __restrict__ we, const float* __restrict__ pe,
                              const float* __restrict__ te, const float* __restrict__ g,
                              const float* __restrict__ b) {
    int tok = blockIdx.x, t = threadIdx.x;
    int id = ids[tok];
    int s  = tok % Ss;
    int ty = tt[tok];
    float x = we[(size_t)id * Hh + t] + pe[(size_t)s * Hh + t] + te[(size_t)ty * Hh + t];
    float2 mv = block_meanvar(x);
    g_h[(size_t)tok * Hh + t] = g[t] * (x - mv.x) * rsqrtf(mv.y + 1e-12f) + b[t];
}

__global__ void eecx_add_ln(const float* __restrict__ res, const float* __restrict__ proj,
                            const float* __restrict__ g, const float* __restrict__ b,
                            float* __restrict__ out) {
    int tok = blockIdx.x, t = threadIdx.x;
    size_t idx = (size_t)tok * Hh + t;
    float x = res[idx] + proj[idx];
    float2 mv = block_meanvar(x);
    out[idx] = g[t] * (x - mv.x) * rsqrtf(mv.y + 1e-12f) + b[t];
}

// ---------------- fp32 -> (hi, lo) bf16 split (4 elems/thread) ---------------
__global__ void eecx_split(const float* __restrict__ x, __nv_bfloat16* __restrict__ hi,
                           __nv_bfloat16* __restrict__ lo, int n4) {
    int i = blockIdx.x * blockDim.x + threadIdx.x;
    if (i >= n4) return;
    float4 v = ((const float4*)x)[i];
    __nv_bfloat16 h0 = __float2bfloat16_rn(v.x);
    __nv_bfloat16 h1 = __float2bfloat16_rn(v.y);
    __nv_bfloat16 h2 = __float2bfloat16_rn(v.z);
    __nv_bfloat16 h3 = __float2bfloat16_rn(v.w);
    __nv_bfloat16 l0 = __float2bfloat16_rn(v.x - __bfloat162float(h0));
    __nv_bfloat16 l1 = __float2bfloat16_rn(v.y - __bfloat162float(h1));
    __nv_bfloat16 l2 = __float2bfloat16_rn(v.z - __bfloat162float(h2));
    __nv_bfloat16 l3 = __float2bfloat16_rn(v.w - __bfloat162float(h3));
    __nv_bfloat162* ph = (__nv_bfloat162*)hi;
    __nv_bfloat162* pl = (__nv_bfloat162*)lo;
    ph[i * 2 + 0] = __nv_bfloat162(h0, h1);
    ph[i * 2 + 1] = __nv_bfloat162(h2, h3);
    pl[i * 2 + 0] = __nv_bfloat162(l0, l1);
    pl[i * 2 + 1] = __nv_bfloat162(l2, l3);
}

// ---------------- W[K,N] fp32 -> Whi_T, Wlo_T [N,K] bf16 ---------------------
__global__ void eecx_prep_w(const float* __restrict__ W, __nv_bfloat16* __restrict__ hiT,
                            __nv_bfloat16* __restrict__ loT, int K, int N) {
    __shared__ float ts[32][33];
    int n0 = blockIdx.x * 32, k0 = blockIdx.y * 32;
    int tx = threadIdx.x, ty = threadIdx.y;  // (32, 8)
    #pragma unroll
    for (int j = 0; j < 32; j += 8)
        ts[ty + j][tx] = W[(size_t)(k0 + ty + j) * N + n0 + tx];
    __syncthreads();
    #pragma unroll
    for (int j = 0; j < 32; j += 8) {
        float v = ts[tx][ty + j];  // = W[k0+tx][n0+ty+j]
        __nv_bfloat16 h = __float2bfloat16_rn(v);
        __nv_bfloat16 l = __float2bfloat16_rn(v - __bfloat162float(h));
        size_t o = (size_t)(n0 + ty + j) * K + k0 + tx;
        hiT[o] = h; loT[o] = l;
    }
}

// ---------------- WMMA bf16x3 GEMM -------------------------------------------
// C[M,N] = A[M,K]fp32 @ W[K,N]fp32 (+bias, opt GELU) via Ahi*Whi+Ahi*Wlo+Alo*Whi.
// A as hi/lo [M,K] bf16 row-major; W as hi/lo [N,K] bf16 row-major (=B col-major).
// CTA = 128x128 C tile, 256 threads = 8 warps (2 m x 4 n), warp = 64x32,
// fragments 16x16x16, fp32 accumulators. K chunks of 32, padded smem staging.
#define AS_LD 40                    // 32 k + 8 pad (bf16 elems, 16B-aligned rows)
#define CS_LD 132                   // 128 + 4 pad (floats)
#define TILE_BYTES (128 * AS_LD * 2)        // 10240 B per tile
#define WG_SMEM (CS_LD * 128 * 4)           // 67584 B (Cs; tiles [4x10240=40960] alias)

__global__ __launch_bounds__(256) void eecx_wgemm(
    const __nv_bfloat16* __restrict__ Ahi, const __nv_bfloat16* __restrict__ Alo,
    const __nv_bfloat16* __restrict__ Whi, const __nv_bfloat16* __restrict__ Wlo,
    const float* __restrict__ bias, float* __restrict__ C,
    int N, int K, int gelu) {
    extern __shared__ char smem[];
    __nv_bfloat16* As_hi = (__nv_bfloat16*)smem;
    __nv_bfloat16* As_lo = As_hi + 128 * AS_LD;
    __nv_bfloat16* Ws_hi = As_lo + 128 * AS_LD;
    __nv_bfloat16* Ws_lo = Ws_hi + 128 * AS_LD;
    float* Cs = (float*)smem;

    int tid = threadIdx.x, wid = tid >> 5;
    int bm = blockIdx.y * 128, bn = blockIdx.x * 128;
    int wm = (wid & 1) * 64;   // warp m-offset (2 blocks of 64)
    int wn = (wid >> 1) * 32;  // warp n-offset (4 blocks of 32)

    wmma::fragment<wmma::accumulator, 16, 16, 16, float> acc[4][2];
    #pragma unroll
    for (int im = 0; im < 4; im++)
        #pragma unroll
        for (int in = 0; in < 2; in++)
            wmma::fill_fragment(acc[im][in], 0.0f);

    for (int kc = 0; kc < K; kc += 32) {
        // stage 4 tiles of [128 rows x 32 bf16]; 512 uint4 per tile, 2/thread
        #pragma unroll
        for (int v = tid; v < 512; v += 256) {
            int row = v >> 2, c8 = (v & 3) * 8;
            size_t ao = (size_t)(bm + row) * K + kc + c8;
            size_t bo = (size_t)(bn + row) * K + kc + c8;
            *(uint4*)&As_hi[row * AS_LD + c8] = *(const uint4*)&Ahi[ao];
            *(uint4*)&As_lo[row * AS_LD + c8] = *(const uint4*)&Alo[ao];
            *(uint4*)&Ws_hi[row * AS_LD + c8] = *(const uint4*)&Whi[bo];
            *(uint4*)&Ws_lo[row * AS_LD + c8] = *(const uint4*)&Wlo[bo];
        }
        __syncthreads();

        #pragma unroll
        for (int kk = 0; kk < 32; kk += 16) {
            wmma::fragment<wmma::matrix_b, 16, 16, 16, __nv_bfloat16, wmma::col_major> bh[2], bl[2];
            #pragma unroll
            for (int in = 0; in < 2; in++) {
                wmma::load_matrix_sync(bh[in], &Ws_hi[(wn + in * 16) * AS_LD + kk], AS_LD);
                wmma::load_matrix_sync(bl[in], &Ws_lo[(wn + in * 16) * AS_LD + kk], AS_LD);
            }
            #pragma unroll
            for (int im = 0; im < 4; im++) {
                wmma::fragment<wmma::matrix_a, 16, 16, 16, __nv_bfloat16, wmma::row_major> ah, al;
                wmma::load_matrix_sync(ah, &As_hi[(wm + im * 16) * AS_LD + kk], AS_LD);
                wmma::load_matrix_sync(al, &As_lo[(wm + im * 16) * AS_LD + kk], AS_LD);
                #pragma unroll
                for (int in = 0; in < 2; in++) {
                    wmma::mma_sync(acc[im][in], ah, bh[in], acc[im][in]);
                    wmma::mma_sync(acc[im][in], ah, bl[in], acc[im][in]);
                    wmma::mma_sync(acc[im][in], al, bh[in], acc[im][in]);
                }
            }
        }
        __syncthreads();
    }

    // stage accumulators to padded smem (aliases the dead tiles), then epilogue
    #pragma unroll
    for (int im = 0; im < 4; im++)
        #pragma unroll
        for (int in = 0; in < 2; in++)
            wmma::store_matrix_sync(&Cs[(wm + im * 16) * CS_LD + wn + in * 16],
                                    acc[im][in], CS_LD, wmma::mem_row_major);
    __syncthreads();

    for (int idx = tid; idx < 128 * 32; idx += 256) {
        int row = idx >> 5, c4 = (idx & 31) * 4;
        float4 v;
        v.x = Cs[row * CS_LD + c4 + 0] + bias[bn + c4 + 0];
        v.y = Cs[row * CS_LD + c4 + 1] + bias[bn + c4 + 1];
        v.z = Cs[row * CS_LD + c4 + 2] + bias[bn + c4 + 2];
        v.w = Cs[row * CS_LD + c4 + 3] + bias[bn + c4 + 3];
        if (gelu) {
            v.x = 0.5f * v.x * (1.0f + erff(v.x * 0.70710678118654752440f));
            v.y = 0.5f * v.y * (1.0f + erff(v.y * 0.70710678118654752440f));
            v.z = 0.5f * v.z * (1.0f + erff(v.z * 0.70710678118654752440f));
            v.w = 0.5f * v.w * (1.0f + erff(v.w * 0.70710678118654752440f));
        }
        *(float4*)&C[(size_t)(bm + row) * N + bn + c4] = v;
    }
}

// ---------------- attention: one block per (batch, head) --------------------
__global__ __launch_bounds__(256) void eecx_attn(const int* __restrict__ amask) {
    extern __shared__ float sm[];
    float* ks = sm;
    float* vs = sm + Ss * DHh;
    float* bs = vs + Ss * DHh;

    int b = blockIdx.x / NHh, hh = blockIdx.x % NHh;
    int t = threadIdx.x;
    size_t base = ((size_t)b * Ss) * Hh + hh * DHh;

    for (int e = t; e < Ss * (DHh / 4); e += 256) {
        int r = e >> 3, c = (e & 7) * 4;
        *(float4*)&ks[r * DHh + c] = *(const float4*)&g_k[base + (size_t)r * Hh + c];
        *(float4*)&vs[r * DHh + c] = *(const float4*)&g_v[base + (size_t)r * Hh + c];
    }
    bs[t] = (1.0f - (float)amask[b * Ss + t]) * -1e9f;
    __syncthreads();

    float q[DHh], o[DHh];
    #pragma unroll
    for (int d = 0; d < DHh; d++) {
        q[d] = g_q[base + (size_t)t * Hh + d];
        o[d] = 0.f;
    }
    float m = -1e30f, l = 0.f;
    const float scale = 0.17677669529663688f;  // 1/sqrt(32)
    for (int j = 0; j < Ss; j++) {
        float s = 0.f;
        #pragma unroll
        for (int d = 0; d < DHh; d++) s += q[d] * ks[j * DHh + d];
        s = s * scale + bs[j];
        float nm = fmaxf(m, s);
        float c = __expf(m - nm);
        float p = __expf(s - nm);
        l = l * c + p;
        #pragma unroll
        for (int d = 0; d < DHh; d++) o[d] = o[d] * c + p * vs[j * DHh + d];
        m = nm;
    }
    float inv = 1.0f / l;
    #pragma unroll
    for (int d = 0; d < DHh; d++)
        g_ctx[base + (size_t)t * Hh + d] = o[d] * inv;
}

// ---------------- early-exit state ------------------------------------------
__global__ void eecx_init_state() {
    int b = threadIdx.x;
    if (b < Bb) { g_active[b] = 1; g_activef[b] = 1.f; g_scores[b] = 0.f; g_exit[b] = 0; }
}

__global__ void eecx_offramp(const float* __restrict__ Wr, const float* __restrict__ br, int layer) {
    int b = blockIdx.x, t = threadIdx.x;  // 128 threads
    __shared__ float sb[4];
    float s = 0.f;
    for (int k = t; k < Hh; k += 128)
        s += g_h[((size_t)b * Ss) * Hh + k] * Wr[layer * Hh + k];
    #pragma unroll
    for (int o = 16; o; o >>= 1) s += __shfl_down_sync(0xffffffffu, s, o);
    if ((t & 31) == 0) sb[t >> 5] = s;
    __syncthreads();
    if (t == 0) {
        float logit = sb[0] + sb[1] + sb[2] + sb[3] + br[layer];
        float a   = fabsf(logit);
        float lp  = fminf(logit, 0.f)  - log1pf(expf(-a));
        float ln_ = fminf(-logit, 0.f) - log1pf(expf(-a));
        float p   = 1.0f / (1.0f + expf(-logit));
        float ent = -(p * lp + (1.0f - p) * ln_);
        if (g_active[b] && ent < 0.1f) {
            g_scores[b] = logit; g_exit[b] = layer;
            g_active[b] = 0;     g_activef[b] = 0.f;
        }
    }
}

__global__ void eecx_mask_h() {  // h *= active
    size_t i = (size_t)blockIdx.x * blockDim.x + threadIdx.x;
    int b = (int)(i / (Ss * Hh / 4));
    float a = g_activef[b];
    float4* p = (float4*)g_h;
    float4 v = p[i];
    v.x *= a; v.y *= a; v.z *= a; v.w *= a;
    p[i] = v;
}

// ---------------- pooler / classifier / output ------------------------------
__global__ void eecx_pooler(const float* __restrict__ Wp, const float* __restrict__ bp) {
    __shared__ float hs[Hh];
    int b = blockIdx.x, t = threadIdx.x;  // 384 threads
    hs[t] = g_h[((size_t)b * Ss) * Hh + t];
    __syncthreads();
    float s = bp[t];
    for (int k = 0; k < Hh; k++) s += hs[k] * Wp[(size_t)k * Hh + t];
    g_pooled[b * Hh + t] = tanhf(s);
}

__global__ void eecx_classifier(const float* __restrict__ Wc, const float* __restrict__ bc) {
    int b = blockIdx.x, t = threadIdx.x;  // 128 threads
    __shared__ float sb[4];
    float s = 0.f;
    for (int k = t; k < Hh; k += 128) s += g_pooled[b * Hh + k] * Wc[k];
    #pragma unroll
    for (int o = 16; o; o >>= 1) s += __shfl_down_sync(0xffffffffu, s, o);
    if ((t & 31) == 0) sb[t >> 5] = s;
    __syncthreads();
    if (t == 0) {
        float fl = sb[0] + sb[1] + sb[2] + sb[3] + bc[0];
        if (g_active[b]) { g_scores[b] = fl; g_exit[b] = NOFF; }
    }
}

__global__ void eecx_write_out(float* __restrict__ out, int out_size) {
    __shared__ int cnt[NOFF + 1];
    int t = threadIdx.x;  // 256 threads
    if (t <= NOFF) cnt[t] = 0;
    __syncthreads();
    if (t < Bb) atomicAdd(&cnt[g_exit[t]], 1);
    __syncthreads();
    if (t < Bb) {
        if (t < out_size)       out[t]       = g_scores[t];
        if (Bb + t < out_size)  out[Bb + t]  = (float)g_exit[t];
    }
    if (t <= NOFF && 2 * Bb + t < out_size) out[2 * Bb + t] = (float)cnt[t];
}

// ---------------- host ------------------------------------------------------
extern "C" void kernel_launch(void* const* d_in, const int* in_sizes, int n_in,
                              void* d_out, int out_size) {
    const int*   ids   = (const int*)d_in[0];
    const int*   amask = (const int*)d_in[1];
    const int*   tt    = (const int*)d_in[2];
    const float* we    = (const float*)d_in[3];
    const float* pe    = (const float*)d_in[4];
    const float* te    = (const float*)d_in[5];
    const float* eg    = (const float*)d_in[6];
    const float* eb    = (const float*)d_in[7];
    const float* Wq    = (const float*)d_in[8];
    const float* bq    = (const float*)d_in[9];
    const float* Wk    = (const float*)d_in[10];
    const float* bk    = (const float*)d_in[11];
    const float* Wv    = (const float*)d_in[12];
    const float* bv    = (const float*)d_in[13];
    const float* Wo    = (const float*)d_in[14];
    const float* bo    = (const float*)d_in[15];
    const float* g1    = (const float*)d_in[16];
    const float* b1    = (const float*)d_in[17];
    const float* Wi    = (const float*)d_in[18];
    const float* bi    = (const float*)d_in[19];
    const float* Wf    = (const float*)d_in[20];
    const float* bf    = (const float*)d_in[21];
    const float* g2    = (const float*)d_in[22];
    const float* b2    = (const float*)d_in[23];
    const float* Wp    = (const float*)d_in[24];
    const float* bp    = (const float*)d_in[25];
    const float* Wc    = (const float*)d_in[26];
    const float* bc    = (const float*)d_in[27];
    const float* Wr    = (const float*)d_in[28];
    const float* br    = (const float*)d_in[29];
    float* out = (float*)d_out;

    float *ph, *pq, *pk, *pv, *pctx, *ptmp, *pffn;
    __nv_bfloat16 *pxh, *pxl, *pwh, *pwl;
    cudaGetSymbolAddress((void**)&ph,   g_h);
    cudaGetSymbolAddress((void**)&pq,   g_q);
    cudaGetSymbolAddress((void**)&pk,   g_k);
    cudaGetSymbolAddress((void**)&pv,   g_v);
    cudaGetSymbolAddress((void**)&pctx, g_ctx);
    cudaGetSymbolAddress((void**)&ptmp, g_tmp);
    cudaGetSymbolAddress((void**)&pffn, g_ffn);
    cudaGetSymbolAddress((void**)&pxh,  g_xhi);
    cudaGetSymbolAddress((void**)&pxl,  g_xlo);
    cudaGetSymbolAddress((void**)&pwh,  g_whiT);
    cudaGetSymbolAddress((void**)&pwl,  g_wloT);

    const int ATTN_SMEM = (Ss * DHh * 2 + Ss) * 4;  // 66560 B
    cudaFuncSetAttribute(eecx_attn,  cudaFuncAttributeMaxDynamicSharedMemorySize, ATTN_SMEM);
    cudaFuncSetAttribute(eecx_wgemm, cudaFuncAttributeMaxDynamicSharedMemorySize, WG_SMEM);

    eecx_init_state<<<1, 128>>>();
    eecx_embed_ln<<<TOK, Hh>>>(ids, tt, we, pe, te, eg, eb);

    dim3 tpb(32, 8);
    dim3 gWp(Hh / 32, Hh / 32);    // 384x384 weights
    dim3 gWi(Ff / 32, Hh / 32);    // Wi: K=384, N=1536
    dim3 gWf(Hh / 32, Ff / 32);    // Wf: K=1536, N=384
    dim3 gG384(Hh / 128, TOK / 128);   // N=384 GEMM tiles: 3 x 256
    dim3 gG1536(Ff / 128, TOK / 128);  // N=1536 GEMM tiles: 12 x 256
    const int n4h = TOK * Hh / 4, n4f = TOK * Ff / 4;
    const int SPB = 256;

    for (int i = 0; i < Ll; i++) {
        const float* wq = Wq + (size_t)i * Hh * Hh;
        const float* wk = Wk + (size_t)i * Hh * Hh;
        const float* wv = Wv + (size_t)i * Hh * Hh;
        const float* wo = Wo + (size_t)i * Hh * Hh;
        const float* wi = Wi + (size_t)i * Hh * Ff;
        const float* wf = Wf + (size_t)i * Ff * Hh;

        // QKV
        eecx_split<<<(n4h + SPB - 1) / SPB, SPB>>>(ph, pxh, pxl, n4h);
        eecx_prep_w<<<gWp, tpb>>>(wq, pwh, pwl, Hh, Hh);
        eecx_wgemm<<<gG384, 256, WG_SMEM>>>(pxh, pxl, pwh, pwl, bq + i * Hh, pq, Hh, Hh, 0);
        eecx_prep_w<<<gWp, tpb>>>(wk, pwh, pwl, Hh, Hh);
        eecx_wgemm<<<gG384, 256, WG_SMEM>>>(pxh, pxl, pwh, pwl, bk + i * Hh, pk, Hh, Hh, 0);
        eecx_prep_w<<<gWp, tpb>>>(wv, pwh, pwl, Hh, Hh);
        eecx_wgemm<<<gG384, 256, WG_SMEM>>>(pxh, pxl, pwh, pwl, bv + i * Hh, pv, Hh, Hh, 0);
        eecx_attn<<<Bb * NHh, 256, ATTN_SMEM>>>(amask);
        // O projection
        eecx_split<<<(n4h + SPB - 1) / SPB, SPB>>>(pctx, pxh, pxl, n4h);
        eecx_prep_w<<<gWp, tpb>>>(wo, pwh, pwl, Hh, Hh);
        eecx_wgemm<<<gG384, 256, WG_SMEM>>>(pxh, pxl, pwh, pwl, bo + i * Hh, ptmp, Hh, Hh, 0);
        eecx_add_ln<<<TOK, Hh>>>(ph, ptmp, g1 + i * Hh, b1 + i * Hh, ph);
        // FFN
        eecx_split<<<(n4h + SPB - 1) / SPB, SPB>>>(ph, pxh, pxl, n4h);
        eecx_prep_w<<<gWi, tpb>>>(wi, pwh, pwl, Hh, Ff);
        eecx_wgemm<<<gG1536, 256, WG_SMEM>>>(pxh, pxl, pwh, pwl, bi + (size_t)i * Ff, pffn, Ff, Hh, 1);
        eecx_split<<<(n4f + SPB - 1) / SPB, SPB>>>(pffn, pxh, pxl, n4f);
        eecx_prep_w<<<gWf, tpb>>>(wf, pwh, pwl, Ff, Hh);
        eecx_wgemm<<<gG384, 256, WG_SMEM>>>(pxh, pxl, pwh, pwl, bf + i * Hh, ptmp, Hh, Ff, 0);
        eecx_add_ln<<<TOK, Hh>>>(ph, ptmp, g2 + i * Hh, b2 + i * Hh, ph);

        if (i < NOFF) {
            eecx_offramp<<<Bb, 128>>>(Wr, br, i);
            eecx_mask_h<<<(TOK * Hh / 4) / 256, 256>>>();
        }
    }

    eecx_pooler<<<Bb, Hh>>>(Wp, bp);
    eecx_classifier<<<Bb, 128>>>(Wc, bc);
    eecx_write_out<<<1, 256>>>(out, out_size);
}